// round 7
// baseline (speedup 1.0000x reference)
#include <cuda_runtime.h>
#include <cstdint>
#include <cfloat>
#include <climits>

#define B_  16384
#define TD_ 4096
#define L_  1024
#define K_  8192
#define O_  128
#define LW_ (L_ / 4)          // 256 uint32 words per row (4 int8 each)

#define CAND_MAX 16
#define CB_SCALE 1040384.0f   // 127 * 8192 ; |cb| < 1/8192 strictly => fits int8
#define W_DOT    1e-3f        // capture window in dot units (err bound ~2e-4)

// ---------------- scratch (device globals) -----------------------------------
__device__ float   g_ze[(size_t)B_ * L_];       // 64 MB fp32 z_e
__device__ float   g_zq[(size_t)B_ * L_];       // 64 MB fp32 z_q
__device__ int     g_dti[(size_t)B_ * K_];      // 512 MB int dot products
__device__ uint32_t g_zq8[(size_t)B_ * LW_];    // 16 MB packed int8 z
__device__ uint32_t g_cb8[(size_t)K_ * LW_];    // 8 MB packed int8 codebook
__device__ float   g_zscale[B_];
__device__ float   g_P[B_];
__device__ float   g_c[K_];
__device__ int     g_rowmax[B_];
__device__ int     g_idx[B_];
__device__ int     g_cand2[(size_t)B_ * CAND_MAX];
__device__ int     g_ncand[B_];
__device__ double  g_rowloss[B_];

// ================= int8 quantization =========================================
// per-row scale: 127 / max|z_row| ; packs 4 int8 per uint32, coalesced
__global__ void zquant_kernel(void)
{
    int row  = blockIdx.x * (blockDim.x >> 5) + (threadIdx.x >> 5);
    int lane = threadIdx.x & 31;
    const float* z = g_ze + (size_t)row * L_;

    float4 v[8];
    float m = 0.0f;
    #pragma unroll
    for (int i = 0; i < 8; i++) {
        v[i] = *(const float4*)(z + lane * 4 + i * 128);
        m = fmaxf(m, fmaxf(fmaxf(fabsf(v[i].x), fabsf(v[i].y)),
                           fmaxf(fabsf(v[i].z), fabsf(v[i].w))));
    }
    #pragma unroll
    for (int o = 16; o > 0; o >>= 1)
        m = fmaxf(m, __shfl_xor_sync(0xffffffffu, m, o));
    float scale = 127.0f / fmaxf(m, 1e-20f);

    uint32_t* dst = g_zq8 + (size_t)row * LW_;
    #pragma unroll
    for (int i = 0; i < 8; i++) {
        int a = (int)rintf(v[i].x * scale);
        int b = (int)rintf(v[i].y * scale);
        int c = (int)rintf(v[i].z * scale);
        int d = (int)rintf(v[i].w * scale);
        uint32_t w = (uint32_t)(a & 0xFF) | ((uint32_t)(b & 0xFF) << 8)
                   | ((uint32_t)(c & 0xFF) << 16) | ((uint32_t)(d & 0xFF) << 24);
        dst[lane + i * 32] = w;
    }
    if (lane == 0) g_zscale[row] = scale;
}

__global__ void cbquant_kernel(const float* __restrict__ cb)
{
    size_t wi = (size_t)blockIdx.x * blockDim.x + threadIdx.x;
    const float4 v = *(const float4*)(cb + wi * 4);
    int a = (int)rintf(v.x * CB_SCALE);
    int b = (int)rintf(v.y * CB_SCALE);
    int c = (int)rintf(v.z * CB_SCALE);
    int d = (int)rintf(v.w * CB_SCALE);
    g_cb8[wi] = (uint32_t)(a & 0xFF) | ((uint32_t)(b & 0xFF) << 8)
              | ((uint32_t)(c & 0xFF) << 16) | ((uint32_t)(d & 0xFF) << 24);
}

__global__ void init_rowmax_kernel(void)
{
    int i = blockIdx.x * blockDim.x + threadIdx.x;
    g_rowmax[i] = INT_MIN;
}

// ================= int8 dp4a dot GEMM: g_dti = zq8 @ cb8^T ===================
// 128x128 tile, BK = 8 words (32 int8-k). Same proven SGEMM skeleton.
__global__ __launch_bounds__(256) void dist_i8_kernel(void)
{
    const int BK = 8;
    __shared__ uint32_t As[BK][128];
    __shared__ uint32_t Bs[BK][128];
    __shared__ int      sv[128][16];

    int bm = blockIdx.y * 128, bn = blockIdx.x * 128;
    int tid = threadIdx.x;
    int tx = tid & 15, ty = tid >> 4;
    int lrow = tid >> 1, lcol = (tid & 1) * 4;

    const uint32_t* Aptr = g_zq8 + (size_t)(bm + lrow) * LW_ + lcol;
    const uint32_t* Bptr = g_cb8 + (size_t)(bn + lrow) * LW_ + lcol;

    int acc[8][8];
    #pragma unroll
    for (int i = 0; i < 8; i++)
        #pragma unroll
        for (int j = 0; j < 8; j++) acc[i][j] = 0;

    for (int k0 = 0; k0 < LW_; k0 += BK) {
        uint4 av = *(const uint4*)(Aptr + k0);
        uint4 bv = *(const uint4*)(Bptr + k0);
        As[lcol + 0][lrow] = av.x; As[lcol + 1][lrow] = av.y;
        As[lcol + 2][lrow] = av.z; As[lcol + 3][lrow] = av.w;
        Bs[lcol + 0][lrow] = bv.x; Bs[lcol + 1][lrow] = bv.y;
        Bs[lcol + 2][lrow] = bv.z; Bs[lcol + 3][lrow] = bv.w;
        __syncthreads();
        #pragma unroll
        for (int kk = 0; kk < BK; kk++) {
            uint32_t ar[8], br[8];
            #pragma unroll
            for (int i = 0; i < 8; i++) ar[i] = As[kk][ty * 8 + i];
            #pragma unroll
            for (int j = 0; j < 8; j++) br[j] = Bs[kk][tx * 8 + j];
            #pragma unroll
            for (int i = 0; i < 8; i++)
                #pragma unroll
                for (int j = 0; j < 8; j++)
                    acc[i][j] = __dp4a((int)ar[i], (int)br[j], acc[i][j]);
        }
        __syncthreads();
    }

    // store tile + per-row max
    #pragma unroll
    for (int i = 0; i < 8; i++) {
        int r = bm + ty * 8 + i;
        int rm = acc[i][0];
        #pragma unroll
        for (int j = 0; j < 8; j += 4) {
            int4 o = make_int4(acc[i][j], acc[i][j + 1], acc[i][j + 2], acc[i][j + 3]);
            *(int4*)&g_dti[(size_t)r * K_ + bn + tx * 8 + j] = o;
        }
        #pragma unroll
        for (int j = 1; j < 8; j++) rm = max(rm, acc[i][j]);
        sv[ty * 8 + i][tx] = rm;
    }
    __syncthreads();
    if (tid < 128) {
        int m = sv[tid][0];
        #pragma unroll
        for (int t = 1; t < 16; t++) m = max(m, sv[tid][t]);
        atomicMax(&g_rowmax[bm + tid], m);
    }
}

// ================= candidate collection (single pass over g_dti) =============
__global__ void scan_kernel(void)
{
    int w = threadIdx.x >> 5, lane = threadIdx.x & 31;
    int row = blockIdx.x * 8 + w;
    const int* d = g_dti + (size_t)row * K_;

    int W = (int)(W_DOT * g_zscale[row] * CB_SCALE) + 1;
    int thr = g_rowmax[row] - W;

    int cnt = 0;
    for (int j0 = 0; j0 < K_; j0 += 128) {
        int4 v = *(const int4*)(d + j0 + lane * 4);
        int dv[4] = { v.x, v.y, v.z, v.w };
        #pragma unroll
        for (int e = 0; e < 4; e++) {
            unsigned mask = __ballot_sync(0xffffffffu, dv[e] >= thr);
            if (dv[e] >= thr) {
                int slot = cnt + __popc(mask & ((1u << lane) - 1u));
                if (slot < CAND_MAX)
                    g_cand2[(size_t)row * CAND_MAX + slot] = j0 + lane * 4 + e;
            }
            cnt += __popc(mask);
        }
    }
    if (lane == 0) g_ncand[row] = cnt;
}

// ================= exact refinement (proven sequential-fp32 chain) ===========
__global__ void refine_kernel(const float* __restrict__ cb,
                              float* __restrict__ out_idx_f, int write_idx)
{
    int w = threadIdx.x >> 5, lane = threadIdx.x & 31;
    int row = blockIdx.x * 8 + w;
    const float* ze = g_ze + (size_t)row * L_;
    float P = g_P[row];
    int cnt = g_ncand[row];

    float bd = FLT_MAX; int bi = 0x7FFFFFFF;
    if (cnt <= CAND_MAX) {
        if (lane < cnt) {
            int col = g_cand2[(size_t)row * CAND_MAX + lane];
            const float* e = cb + (size_t)col * L_;
            float s = 0.0f;
            #pragma unroll 4
            for (int k = 0; k < L_; k++) s = fmaf(__ldg(&ze[k]), __ldg(&e[k]), s);
            float t = P - 2.0f * s;
            bd = t + __ldg(&g_c[col]);
            bi = col;
        }
    } else {
        for (int col = lane; col < K_; col += 32) {
            const float* e = cb + (size_t)col * L_;
            float s = 0.0f;
            #pragma unroll 4
            for (int k = 0; k < L_; k++) s = fmaf(__ldg(&ze[k]), __ldg(&e[k]), s);
            float t = P - 2.0f * s;
            float dv = t + __ldg(&g_c[col]);
            if (dv < bd || (dv == bd && col < bi)) { bd = dv; bi = col; }
        }
    }
    #pragma unroll
    for (int o = 16; o > 0; o >>= 1) {
        float od = __shfl_xor_sync(0xffffffffu, bd, o);
        int oi = __shfl_xor_sync(0xffffffffu, bi, o);
        if (od < bd || (od == bd && oi < bi)) { bd = od; bi = oi; }
    }
    if (lane == 0) {
        g_idx[row] = bi;
        if (write_idx) out_idx_f[row] = (float)bi;
    }
}

// ================= proven fp32 SGEMM (z_e and classifier) ====================
__global__ __launch_bounds__(256) void sgemm_nt_bias(
    const float* __restrict__ A, const float* __restrict__ Bm,
    const float* __restrict__ bias, float* __restrict__ C,
    int M, int N, int Kd)
{
    const int BK = 8;
    __shared__ float As[BK][128];
    __shared__ float Bs[BK][128];
    int bm = blockIdx.y * 128, bn = blockIdx.x * 128;
    int tid = threadIdx.x;
    int tx = tid & 15, ty = tid >> 4;
    int lrow = tid >> 1, lcol = (tid & 1) * 4;
    const float* Aptr = A  + (size_t)(bm + lrow) * Kd + lcol;
    const float* Bptr = Bm + (size_t)(bn + lrow) * Kd + lcol;
    float acc[8][8];
    #pragma unroll
    for (int i = 0; i < 8; i++)
        #pragma unroll
        for (int j = 0; j < 8; j++) acc[i][j] = 0.0f;
    for (int k0 = 0; k0 < Kd; k0 += BK) {
        float4 av = *(const float4*)(Aptr + k0);
        float4 bv = *(const float4*)(Bptr + k0);
        As[lcol + 0][lrow] = av.x; As[lcol + 1][lrow] = av.y;
        As[lcol + 2][lrow] = av.z; As[lcol + 3][lrow] = av.w;
        Bs[lcol + 0][lrow] = bv.x; Bs[lcol + 1][lrow] = bv.y;
        Bs[lcol + 2][lrow] = bv.z; Bs[lcol + 3][lrow] = bv.w;
        __syncthreads();
        #pragma unroll
        for (int kk = 0; kk < BK; kk++) {
            float ar[8], br[8];
            #pragma unroll
            for (int i = 0; i < 8; i++) ar[i] = As[kk][ty * 8 + i];
            #pragma unroll
            for (int j = 0; j < 8; j++) br[j] = Bs[kk][tx * 8 + j];
            #pragma unroll
            for (int i = 0; i < 8; i++)
                #pragma unroll
                for (int j = 0; j < 8; j++)
                    acc[i][j] = fmaf(ar[i], br[j], acc[i][j]);
        }
        __syncthreads();
    }
    #pragma unroll
    for (int i = 0; i < 8; i++) {
        int r = bm + ty * 8 + i;
        #pragma unroll
        for (int j = 0; j < 8; j += 4) {
            int c = bn + tx * 8 + j;
            float4 o;
            o.x = acc[i][j + 0] + bias[c + 0];
            o.y = acc[i][j + 1] + bias[c + 1];
            o.z = acc[i][j + 2] + bias[c + 2];
            o.w = acc[i][j + 3] + bias[c + 3];
            *(float4*)&C[(size_t)r * N + c] = o;
        }
    }
}

// ================= proven small kernels ======================================
__global__ void rowsumsq_kernel(const float* __restrict__ src, float* __restrict__ dst,
                                int rows, int cols)
{
    int row  = blockIdx.x * (blockDim.x >> 5) + (threadIdx.x >> 5);
    int lane = threadIdx.x & 31;
    if (row >= rows) return;
    const float* r = src + (size_t)row * cols;
    double s = 0.0;
    for (int j = lane; j < cols; j += 32) {
        float v = r[j];
        s += (double)v * (double)v;
    }
    #pragma unroll
    for (int o = 16; o > 0; o >>= 1) s += __shfl_down_sync(0xffffffffu, s, o);
    if (lane == 0) dst[row] = (float)s;
}

__global__ void loss_zq_kernel(const float* __restrict__ cb)
{
    int row = blockIdx.x;
    const float* ze = g_ze + (size_t)row * L_;
    const float* q  = cb   + (size_t)g_idx[row] * L_;
    float* zq = g_zq + (size_t)row * L_;
    double s = 0.0;
    for (int j = threadIdx.x; j < L_; j += blockDim.x) {
        float z = ze[j], qq = q[j];
        float dlt = qq - z;
        s += (double)dlt * (double)dlt;
        zq[j] = z + dlt;
    }
    __shared__ double sh[256];
    sh[threadIdx.x] = s;
    __syncthreads();
    for (int o = 128; o > 0; o >>= 1) {
        if (threadIdx.x < o) sh[threadIdx.x] += sh[threadIdx.x + o];
        __syncthreads();
    }
    if (threadIdx.x == 0) g_rowloss[row] = sh[0];
}

__global__ void loss_reduce_kernel(float* __restrict__ out_loss)
{
    __shared__ double sh[256];
    double s = 0.0;
    for (int r = threadIdx.x; r < B_; r += 256) s += g_rowloss[r];
    sh[threadIdx.x] = s;
    __syncthreads();
    for (int o = 128; o > 0; o >>= 1) {
        if (threadIdx.x < o) sh[threadIdx.x] += sh[threadIdx.x + o];
        __syncthreads();
    }
    if (threadIdx.x == 0) {
        float m = (float)(sh[0] / ((double)B_ * (double)L_));
        out_loss[0] = m + 0.25f * m;
    }
}

__global__ void softmax_kernel(float* __restrict__ logits)
{
    int row = blockIdx.x;
    float* p = logits + (size_t)row * O_;
    float v = p[threadIdx.x];
    __shared__ float shm[4];
    float m = v;
    #pragma unroll
    for (int o = 16; o > 0; o >>= 1) m = fmaxf(m, __shfl_xor_sync(0xffffffffu, m, o));
    if ((threadIdx.x & 31) == 0) shm[threadIdx.x >> 5] = m;
    __syncthreads();
    float mm = fmaxf(fmaxf(shm[0], shm[1]), fmaxf(shm[2], shm[3]));
    __syncthreads();
    float e = expf(v - mm);
    float s = e;
    #pragma unroll
    for (int o = 16; o > 0; o >>= 1) s += __shfl_xor_sync(0xffffffffu, s, o);
    if ((threadIdx.x & 31) == 0) shm[threadIdx.x >> 5] = s;
    __syncthreads();
    float ss = shm[0] + shm[1] + shm[2] + shm[3];
    p[threadIdx.x] = e / ss;
}

// ================= launch =====================================================
extern "C" void kernel_launch(void* const* d_in, const int* in_sizes, int n_in,
                              void* d_out, int out_size)
{
    const float* x     = (const float*)d_in[0];
    const float* W_enc = (const float*)d_in[1];
    const float* b_enc = (const float*)d_in[2];
    const float* cb    = (const float*)d_in[3];
    const float* W_cls = (const float*)d_in[4];
    const float* b_cls = (const float*)d_in[5];
    float* out = (float*)d_out;

    float* out_logits = out;
    float* out_loss   = out + (size_t)B_ * O_;
    float* out_idx    = out + (size_t)B_ * O_ + 1;
    int has_loss = (out_size >= B_ * O_ + 1);
    int has_idx  = (out_size >= B_ * O_ + 1 + B_);

    void *p;
    float *ze, *zq, *Pv, *cv;
    cudaGetSymbolAddress(&p, g_ze); ze = (float*)p;
    cudaGetSymbolAddress(&p, g_zq); zq = (float*)p;
    cudaGetSymbolAddress(&p, g_P);  Pv = (float*)p;
    cudaGetSymbolAddress(&p, g_c);  cv = (float*)p;

    // prep: codebook norms + int8 codebook
    rowsumsq_kernel<<<K_ / 8, 256>>>(cb, cv, K_, L_);
    cbquant_kernel<<<(unsigned)((size_t)K_ * L_ / 4 / 256), 256>>>(cb);
    init_rowmax_kernel<<<B_ / 256, 256>>>();

    // z_e: proven sequential-k fp32 SGEMM
    {
        dim3 grid(L_ / 128, B_ / 128);
        sgemm_nt_bias<<<grid, 256>>>(x, W_enc, b_enc, ze, B_, L_, TD_);
    }
    rowsumsq_kernel<<<B_ / 8, 256>>>(ze, Pv, B_, L_);
    zquant_kernel<<<B_ / 8, 256>>>();

    // int8 dp4a dot GEMM + rowmax, then collect + exact refine
    {
        dim3 grid(K_ / 128, B_ / 128);
        dist_i8_kernel<<<grid, 256>>>();
    }
    scan_kernel<<<B_ / 8, 256>>>();
    refine_kernel<<<B_ / 8, 256>>>(cb, out_idx, has_idx);

    // loss + z_q (proven R1 path)
    loss_zq_kernel<<<B_, 256>>>(cb);
    if (has_loss) loss_reduce_kernel<<<1, 256>>>(out_loss);

    // classifier + softmax (proven R1 path)
    {
        dim3 grid(O_ / 128, B_ / 128);
        sgemm_nt_bias<<<grid, 256>>>(zq, W_cls, b_cls, out_logits, B_, O_, L_);
    }
    softmax_kernel<<<B_, 128>>>(out_logits);
}

// round 9
// speedup vs baseline: 2.4730x; 2.4730x over previous
#include <cuda_runtime.h>
#include <cuda_fp16.h>
#include <cstdint>
#include <cfloat>

#define B_  16384
#define TD_ 4096
#define L_  1024
#define K_  8192
#define O_  128
#define LW2 (L_ / 2)          // 512 half2 words per row

#define CAND_MAX 16
#define WIN_DOTP 2.0f         // capture window in scaled-dot units (8192*dot)

// ---------------- scratch (device globals) -----------------------------------
__device__ float    g_ze[(size_t)B_ * L_];      // 64 MB fp32 z_e
__device__ float    g_zq[(size_t)B_ * L_];      // 64 MB fp32 z_q
__device__ float    g_dotf[(size_t)B_ * K_];    // 512 MB scaled approx dots
__device__ __half2  g_zh[(size_t)B_ * LW2];     // 32 MB packed half2 z
__device__ __half2  g_cbh[(size_t)K_ * LW2];    // 16 MB packed half2 codebook*8192
__device__ float    g_P[B_];
__device__ float    g_c[K_];
__device__ uint32_t g_rowmax[B_];               // monotonic float keys
__device__ int      g_idx[B_];
__device__ int      g_cand2[(size_t)B_ * CAND_MAX];
__device__ int      g_ncand[B_];
__device__ double   g_rowloss[B_];

// monotonic float<->uint key (order-preserving under unsigned compare)
__device__ __forceinline__ uint32_t fkey(float f) {
    uint32_t b = __float_as_uint(f);
    return (b & 0x80000000u) ? ~b : (b | 0x80000000u);
}
__device__ __forceinline__ float finv(uint32_t u) {
    uint32_t b = (u & 0x80000000u) ? (u & 0x7fffffffu) : ~u;
    return __uint_as_float(b);
}

// ================= half2 conversions =========================================
__global__ void zhalf_kernel(void)
{
    size_t i = (size_t)blockIdx.x * blockDim.x + threadIdx.x;   // half2 word idx
    const float2 v = *(const float2*)(g_ze + i * 2);
    g_zh[i] = __floats2half2_rn(v.x, v.y);
}

__global__ void cbhalf_kernel(const float* __restrict__ cb)
{
    size_t i = (size_t)blockIdx.x * blockDim.x + threadIdx.x;
    const float2 v = *(const float2*)(cb + i * 2);
    g_cbh[i] = __floats2half2_rn(v.x * 8192.0f, v.y * 8192.0f);
}

__global__ void init_rowmax_kernel(void)
{
    int i = blockIdx.x * blockDim.x + threadIdx.x;
    g_rowmax[i] = 0u;
}

// ================= half2 HFMA2 dot GEMM: g_dotf = (zh @ cbh^T) ===============
// 128x128 tile, BK = 8 half2 words (16 halves). Proven SGEMM skeleton.
__global__ __launch_bounds__(256) void dist_h2_kernel(void)
{
    const int BK = 8;
    __shared__ __half2   As[BK][128];
    __shared__ __half2   Bs[BK][128];
    __shared__ uint32_t  sv[128][16];

    int bm = blockIdx.y * 128, bn = blockIdx.x * 128;
    int tid = threadIdx.x;
    int tx = tid & 15, ty = tid >> 4;
    int lrow = tid >> 1, lcol = (tid & 1) * 4;

    const __half2* Aptr = g_zh  + (size_t)(bm + lrow) * LW2 + lcol;
    const __half2* Bptr = g_cbh + (size_t)(bn + lrow) * LW2 + lcol;

    __half2 acc[8][8];
    #pragma unroll
    for (int i = 0; i < 8; i++)
        #pragma unroll
        for (int j = 0; j < 8; j++) acc[i][j] = __floats2half2_rn(0.f, 0.f);

    for (int k0 = 0; k0 < LW2; k0 += BK) {
        // 16B vector load of 4 half2
        float4 avf = *(const float4*)(Aptr + k0);
        float4 bvf = *(const float4*)(Bptr + k0);
        const __half2* av = (const __half2*)&avf;
        const __half2* bv = (const __half2*)&bvf;
        As[lcol + 0][lrow] = av[0]; As[lcol + 1][lrow] = av[1];
        As[lcol + 2][lrow] = av[2]; As[lcol + 3][lrow] = av[3];
        Bs[lcol + 0][lrow] = bv[0]; Bs[lcol + 1][lrow] = bv[1];
        Bs[lcol + 2][lrow] = bv[2]; Bs[lcol + 3][lrow] = bv[3];
        __syncthreads();
        #pragma unroll
        for (int kk = 0; kk < BK; kk++) {
            __half2 ar[8], br[8];
            // two 16B vector loads each (4 half2 per load)
            float4 a0f = *(const float4*)&As[kk][ty * 8];
            float4 a1f = *(const float4*)&As[kk][ty * 8 + 4];
            float4 b0f = *(const float4*)&Bs[kk][tx * 8];
            float4 b1f = *(const float4*)&Bs[kk][tx * 8 + 4];
            const __half2* a0 = (const __half2*)&a0f;
            const __half2* a1 = (const __half2*)&a1f;
            const __half2* b0 = (const __half2*)&b0f;
            const __half2* b1 = (const __half2*)&b1f;
            #pragma unroll
            for (int t = 0; t < 4; t++) { ar[t] = a0[t]; ar[t + 4] = a1[t]; }
            #pragma unroll
            for (int t = 0; t < 4; t++) { br[t] = b0[t]; br[t + 4] = b1[t]; }
            #pragma unroll
            for (int i = 0; i < 8; i++)
                #pragma unroll
                for (int j = 0; j < 8; j++)
                    acc[i][j] = __hfma2(ar[i], br[j], acc[i][j]);
        }
        __syncthreads();
    }

    // epilogue: fp32 lane-combine, store dots + per-row max key
    #pragma unroll
    for (int i = 0; i < 8; i++) {
        int r = bm + ty * 8 + i;
        float f[8];
        #pragma unroll
        for (int j = 0; j < 8; j++)
            f[j] = __low2float(acc[i][j]) + __high2float(acc[i][j]);
        #pragma unroll
        for (int j = 0; j < 8; j += 4) {
            float4 o = make_float4(f[j], f[j + 1], f[j + 2], f[j + 3]);
            *(float4*)&g_dotf[(size_t)r * K_ + bn + tx * 8 + j] = o;
        }
        uint32_t rm = fkey(f[0]);
        #pragma unroll
        for (int j = 1; j < 8; j++) rm = max(rm, fkey(f[j]));
        sv[ty * 8 + i][tx] = rm;
    }
    __syncthreads();
    if (tid < 128) {
        uint32_t m = sv[tid][0];
        #pragma unroll
        for (int t = 1; t < 16; t++) m = max(m, sv[tid][t]);
        atomicMax(&g_rowmax[bm + tid], m);
    }
}

// ================= candidate collection (single pass, max-dot) ===============
__global__ void scan_kernel(void)
{
    int w = threadIdx.x >> 5, lane = threadIdx.x & 31;
    int row = blockIdx.x * 8 + w;
    const float* d = g_dotf + (size_t)row * K_;

    float thr = finv(g_rowmax[row]) - WIN_DOTP;

    int cnt = 0;
    for (int j0 = 0; j0 < K_; j0 += 128) {
        float4 v = *(const float4*)(d + j0 + lane * 4);
        float dv[4] = { v.x, v.y, v.z, v.w };
        #pragma unroll
        for (int e = 0; e < 4; e++) {
            unsigned mask = __ballot_sync(0xffffffffu, dv[e] >= thr);
            if (dv[e] >= thr) {
                int slot = cnt + __popc(mask & ((1u << lane) - 1u));
                if (slot < CAND_MAX)
                    g_cand2[(size_t)row * CAND_MAX + slot] = j0 + lane * 4 + e;
            }
            cnt += __popc(mask);
        }
    }
    if (lane == 0) g_ncand[row] = cnt;
}

// ================= exact refinement (proven sequential-fp32 chain) ===========
__global__ void refine_kernel(const float* __restrict__ cb,
                              float* __restrict__ out_idx_f, int write_idx)
{
    int w = threadIdx.x >> 5, lane = threadIdx.x & 31;
    int row = blockIdx.x * 8 + w;
    const float* ze = g_ze + (size_t)row * L_;
    float P = g_P[row];
    int cnt = g_ncand[row];

    float bd = FLT_MAX; int bi = 0x7FFFFFFF;
    if (cnt <= CAND_MAX) {
        if (lane < cnt) {
            int col = g_cand2[(size_t)row * CAND_MAX + lane];
            const float* e = cb + (size_t)col * L_;
            float s = 0.0f;
            #pragma unroll 4
            for (int k = 0; k < L_; k++) s = fmaf(__ldg(&ze[k]), __ldg(&e[k]), s);
            float t = P - 2.0f * s;
            bd = t + __ldg(&g_c[col]);
            bi = col;
        }
    } else {
        for (int col = lane; col < K_; col += 32) {
            const float* e = cb + (size_t)col * L_;
            float s = 0.0f;
            #pragma unroll 4
            for (int k = 0; k < L_; k++) s = fmaf(__ldg(&ze[k]), __ldg(&e[k]), s);
            float t = P - 2.0f * s;
            float dv = t + __ldg(&g_c[col]);
            if (dv < bd || (dv == bd && col < bi)) { bd = dv; bi = col; }
        }
    }
    #pragma unroll
    for (int o = 16; o > 0; o >>= 1) {
        float od = __shfl_xor_sync(0xffffffffu, bd, o);
        int oi = __shfl_xor_sync(0xffffffffu, bi, o);
        if (od < bd || (od == bd && oi < bi)) { bd = od; bi = oi; }
    }
    if (lane == 0) {
        g_idx[row] = bi;
        if (write_idx) out_idx_f[row] = (float)bi;
    }
}

// ================= proven fp32 SGEMM (z_e and classifier) ====================
__global__ __launch_bounds__(256) void sgemm_nt_bias(
    const float* __restrict__ A, const float* __restrict__ Bm,
    const float* __restrict__ bias, float* __restrict__ C,
    int M, int N, int Kd)
{
    const int BK = 8;
    __shared__ float As[BK][128];
    __shared__ float Bs[BK][128];
    int bm = blockIdx.y * 128, bn = blockIdx.x * 128;
    int tid = threadIdx.x;
    int tx = tid & 15, ty = tid >> 4;
    int lrow = tid >> 1, lcol = (tid & 1) * 4;
    const float* Aptr = A  + (size_t)(bm + lrow) * Kd + lcol;
    const float* Bptr = Bm + (size_t)(bn + lrow) * Kd + lcol;
    float acc[8][8];
    #pragma unroll
    for (int i = 0; i < 8; i++)
        #pragma unroll
        for (int j = 0; j < 8; j++) acc[i][j] = 0.0f;
    for (int k0 = 0; k0 < Kd; k0 += BK) {
        float4 av = *(const float4*)(Aptr + k0);
        float4 bv = *(const float4*)(Bptr + k0);
        As[lcol + 0][lrow] = av.x; As[lcol + 1][lrow] = av.y;
        As[lcol + 2][lrow] = av.z; As[lcol + 3][lrow] = av.w;
        Bs[lcol + 0][lrow] = bv.x; Bs[lcol + 1][lrow] = bv.y;
        Bs[lcol + 2][lrow] = bv.z; Bs[lcol + 3][lrow] = bv.w;
        __syncthreads();
        #pragma unroll
        for (int kk = 0; kk < BK; kk++) {
            float ar[8], br[8];
            #pragma unroll
            for (int i = 0; i < 8; i++) ar[i] = As[kk][ty * 8 + i];
            #pragma unroll
            for (int j = 0; j < 8; j++) br[j] = Bs[kk][tx * 8 + j];
            #pragma unroll
            for (int i = 0; i < 8; i++)
                #pragma unroll
                for (int j = 0; j < 8; j++)
                    acc[i][j] = fmaf(ar[i], br[j], acc[i][j]);
        }
        __syncthreads();
    }
    #pragma unroll
    for (int i = 0; i < 8; i++) {
        int r = bm + ty * 8 + i;
        #pragma unroll
        for (int j = 0; j < 8; j += 4) {
            int c = bn + tx * 8 + j;
            float4 o;
            o.x = acc[i][j + 0] + bias[c + 0];
            o.y = acc[i][j + 1] + bias[c + 1];
            o.z = acc[i][j + 2] + bias[c + 2];
            o.w = acc[i][j + 3] + bias[c + 3];
            *(float4*)&C[(size_t)r * N + c] = o;
        }
    }
}

// ================= proven small kernels ======================================
__global__ void rowsumsq_kernel(const float* __restrict__ src, float* __restrict__ dst,
                                int rows, int cols)
{
    int row  = blockIdx.x * (blockDim.x >> 5) + (threadIdx.x >> 5);
    int lane = threadIdx.x & 31;
    if (row >= rows) return;
    const float* r = src + (size_t)row * cols;
    double s = 0.0;
    for (int j = lane; j < cols; j += 32) {
        float v = r[j];
        s += (double)v * (double)v;
    }
    #pragma unroll
    for (int o = 16; o > 0; o >>= 1) s += __shfl_down_sync(0xffffffffu, s, o);
    if (lane == 0) dst[row] = (float)s;
}

__global__ void loss_zq_kernel(const float* __restrict__ cb)
{
    int row = blockIdx.x;
    const float* ze = g_ze + (size_t)row * L_;
    const float* q  = cb   + (size_t)g_idx[row] * L_;
    float* zq = g_zq + (size_t)row * L_;
    double s = 0.0;
    for (int j = threadIdx.x; j < L_; j += blockDim.x) {
        float z = ze[j], qq = q[j];
        float dlt = qq - z;
        s += (double)dlt * (double)dlt;
        zq[j] = z + dlt;
    }
    __shared__ double sh[256];
    sh[threadIdx.x] = s;
    __syncthreads();
    for (int o = 128; o > 0; o >>= 1) {
        if (threadIdx.x < o) sh[threadIdx.x] += sh[threadIdx.x + o];
        __syncthreads();
    }
    if (threadIdx.x == 0) g_rowloss[row] = sh[0];
}

__global__ void loss_reduce_kernel(float* __restrict__ out_loss)
{
    __shared__ double sh[256];
    double s = 0.0;
    for (int r = threadIdx.x; r < B_; r += 256) s += g_rowloss[r];
    sh[threadIdx.x] = s;
    __syncthreads();
    for (int o = 128; o > 0; o >>= 1) {
        if (threadIdx.x < o) sh[threadIdx.x] += sh[threadIdx.x + o];
        __syncthreads();
    }
    if (threadIdx.x == 0) {
        float m = (float)(sh[0] / ((double)B_ * (double)L_));
        out_loss[0] = m + 0.25f * m;
    }
}

__global__ void softmax_kernel(float* __restrict__ logits)
{
    int row = blockIdx.x;
    float* p = logits + (size_t)row * O_;
    float v = p[threadIdx.x];
    __shared__ float shm[4];
    float m = v;
    #pragma unroll
    for (int o = 16; o > 0; o >>= 1) m = fmaxf(m, __shfl_xor_sync(0xffffffffu, m, o));
    if ((threadIdx.x & 31) == 0) shm[threadIdx.x >> 5] = m;
    __syncthreads();
    float mm = fmaxf(fmaxf(shm[0], shm[1]), fmaxf(shm[2], shm[3]));
    __syncthreads();
    float e = expf(v - mm);
    float s = e;
    #pragma unroll
    for (int o = 16; o > 0; o >>= 1) s += __shfl_xor_sync(0xffffffffu, s, o);
    if ((threadIdx.x & 31) == 0) shm[threadIdx.x >> 5] = s;
    __syncthreads();
    float ss = shm[0] + shm[1] + shm[2] + shm[3];
    p[threadIdx.x] = e / ss;
}

// ================= launch =====================================================
extern "C" void kernel_launch(void* const* d_in, const int* in_sizes, int n_in,
                              void* d_out, int out_size)
{
    const float* x     = (const float*)d_in[0];
    const float* W_enc = (const float*)d_in[1];
    const float* b_enc = (const float*)d_in[2];
    const float* cb    = (const float*)d_in[3];
    const float* W_cls = (const float*)d_in[4];
    const float* b_cls = (const float*)d_in[5];
    float* out = (float*)d_out;

    float* out_logits = out;
    float* out_loss   = out + (size_t)B_ * O_;
    float* out_idx    = out + (size_t)B_ * O_ + 1;
    int has_loss = (out_size >= B_ * O_ + 1);
    int has_idx  = (out_size >= B_ * O_ + 1 + B_);

    void *p;
    float *ze, *zq, *Pv, *cv;
    cudaGetSymbolAddress(&p, g_ze); ze = (float*)p;
    cudaGetSymbolAddress(&p, g_zq); zq = (float*)p;
    cudaGetSymbolAddress(&p, g_P);  Pv = (float*)p;
    cudaGetSymbolAddress(&p, g_c);  cv = (float*)p;

    // prep: codebook norms + scaled half2 codebook
    rowsumsq_kernel<<<K_ / 8, 256>>>(cb, cv, K_, L_);
    cbhalf_kernel<<<(unsigned)((size_t)K_ * LW2 / 256), 256>>>(cb);
    init_rowmax_kernel<<<B_ / 256, 256>>>();

    // z_e: proven sequential-k fp32 SGEMM
    {
        dim3 grid(L_ / 128, B_ / 128);
        sgemm_nt_bias<<<grid, 256>>>(x, W_enc, b_enc, ze, B_, L_, TD_);
    }
    rowsumsq_kernel<<<B_ / 8, 256>>>(ze, Pv, B_, L_);
    zhalf_kernel<<<(unsigned)((size_t)B_ * LW2 / 256), 256>>>();

    // half2 HFMA2 dot GEMM + rowmax, then collect + exact refine
    {
        dim3 grid(K_ / 128, B_ / 128);
        dist_h2_kernel<<<grid, 256>>>();
    }
    scan_kernel<<<B_ / 8, 256>>>();
    refine_kernel<<<B_ / 8, 256>>>(cb, out_idx, has_idx);

    // loss + z_q (proven path)
    loss_zq_kernel<<<B_, 256>>>(cb);
    if (has_loss) loss_reduce_kernel<<<1, 256>>>(out_loss);

    // classifier + softmax (proven path)
    {
        dim3 grid(O_ / 128, B_ / 128);
        sgemm_nt_bias<<<grid, 256>>>(zq, W_cls, b_cls, out_logits, B_, O_, L_);
    }
    softmax_kernel<<<B_, 128>>>(out_logits);
}